// round 12
// baseline (speedup 1.0000x reference)
#include <cuda_runtime.h>
#include <cstdint>

#define BB 256
#define CC 128
#define TT 64
#define H1 1024
#define H2 1024
#define NC 10

// Scratch device globals (allocation-free rule)
// s1 layout: [b*64+t][h1] int8 {0,1}
__device__ int8_t    g_s1c[(size_t)TT * BB * H1];      // 16MB
__device__ int8_t    g_wl[(size_t)3 * H2 * H1];        // hid_w 3 int8 digits (3MB)
__device__ uint32_t  g_bits[(size_t)TT * BB * 32];     // layer-2 spikes, bit-packed (2MB)

#define WSCALE 2097152.0f           // 2^21
#define WINV   4.76837158203125e-7f // 2^-21

// ---------------------------------------------------------------------------
// helpers
// ---------------------------------------------------------------------------
__device__ __forceinline__ uint32_t smem_u32(const void* p) {
    uint32_t a;
    asm("{ .reg .u64 t; cvta.to.shared.u64 t, %1; cvt.u32.u64 %0, t; }"
        : "=r"(a) : "l"(p));
    return a;
}
__device__ __forceinline__ void cp_async16(uint32_t saddr, const void* gaddr) {
    asm volatile("cp.async.ca.shared.global [%0], [%1], 16;\n"
                 :: "r"(saddr), "l"(gaddr));
}
#define CP_COMMIT() asm volatile("cp.async.commit_group;\n" ::: "memory")
#define CP_WAIT(N)  asm volatile("cp.async.wait_group %0;\n" ::"n"(N) : "memory")

__device__ __forceinline__ void ldm_x4(uint32_t* r, uint32_t addr) {
    asm volatile("ldmatrix.sync.aligned.m8n8.x4.shared.b16 {%0,%1,%2,%3}, [%4];"
                 : "=r"(r[0]), "=r"(r[1]), "=r"(r[2]), "=r"(r[3]) : "r"(addr));
}
// int8 IMMA: D(s32) += A(s8,16x32) * B(s8,32x8)
__device__ __forceinline__ void imma16832(int32_t* c, const uint32_t* a,
                                          uint32_t b0, uint32_t b1) {
    asm volatile(
        "mma.sync.aligned.m16n8k32.row.col.s32.s8.s8.s32 "
        "{%0,%1,%2,%3}, {%4,%5,%6,%7}, {%8,%9}, {%0,%1,%2,%3};"
        : "+r"(c[0]), "+r"(c[1]), "+r"(c[2]), "+r"(c[3])
        : "r"(a[0]), "r"(a[1]), "r"(a[2]), "r"(a[3]), "r"(b0), "r"(b1));
}

// ---------------------------------------------------------------------------
// Kernel 0: quantize hid_w to w_int = round(w*2^21), split into 3 signed
// base-256 digits (exact: w_int = l0*65536 + l1*256 + l2).
// ---------------------------------------------------------------------------
__global__ __launch_bounds__(256) void split_kernel(const float* __restrict__ w) {
    int i = blockIdx.x * 256 + threadIdx.x;
    int wi = __float2int_rn(w[i] * WSCALE);
    int l2 = (wi << 24) >> 24;          // sign-extended low byte
    int t1 = (wi - l2) >> 8;
    int l1 = (t1 << 24) >> 24;
    int l0 = (t1 - l1) >> 8;
    g_wl[i] = (int8_t)l0;
    g_wl[(1 << 20) + i] = (int8_t)l1;
    g_wl[(2 << 20) + i] = (int8_t)l2;
}

// ---------------------------------------------------------------------------
// Kernel A: encoder + layer-1 IF scan (enc_w rank-1).  int8 spike output.
// ---------------------------------------------------------------------------
__global__ __launch_bounds__(256) void enc_scan_kernel(
    const float* __restrict__ x, const float* __restrict__ enc_w,
    const float* __restrict__ enc_b) {
    __shared__ float S[TT];
    __shared__ float red[256];
    int b = blockIdx.x, tid = threadIdx.x;
    const float* xb = x + (size_t)b * CC * TT;
    int t = tid & 63, grp = tid >> 6;
    float a = 0.f;
#pragma unroll
    for (int c = 0; c < 32; c++) a += xb[(grp * 32 + c) * TT + t];
    red[tid] = a;
    __syncthreads();
    if (tid < 64) S[tid] = red[tid] + red[tid + 64] + red[tid + 128] + red[tid + 192];
    __syncthreads();

#pragma unroll
    for (int hh = 0; hh < 4; hh++) {
        int h = hh * 256 + tid;
        float vh = enc_w[(size_t)h * CC];
        float eb = enc_b[h];
        float v = 0.f;
#pragma unroll
        for (int tt = 0; tt < TT; tt++) {
            v += vh * S[tt] + eb;
            bool fire = (v >= 1.0f);
            g_s1c[(size_t)(((b << 6) + tt) << 10) + h] = fire ? 1 : 0;
            if (fire) v = 0.f;
        }
    }
}

// ---------------------------------------------------------------------------
// Kernel B: int8 IMMA GEMM (exact integer) + fused layer-2 IF scan epilogue.
// C-rows m = b*64+t. BM=256 x BN=128, 256 thr / 8 warps (warp 64x64).
// Limb-OUTER: 3 passes over K (16 chunks of K=64 int8), one int32 acc set,
// acc <<= 8 between passes => acc = S0*65536 + S1*256 + S2 exactly.
// 3-stage cp.async pipeline over the 48 flattened (limb,chunk) iterations.
// Epilogue: val = float(acc)*2^-21 -> padded smem [64t][65] -> IF scan ->
// ballot-pack into g_bits.
// ---------------------------------------------------------------------------
#define BM 256
#define BN 128
#define A_BYTES (BM * 80)                    // 20480 (64B rows + 16B pad)
#define B_BYTES (BN * 80)                    // 10240
#define STAGE_BYTES (A_BYTES + B_BYTES)      // 30720
#define GEMM_SMEM 133120                     // max(3*STAGE, 8*64*65*4)

__global__ __launch_bounds__(256, 1) void gemm2_kernel(const float* __restrict__ hid_b) {
    extern __shared__ __align__(128) char smem[];
    const uint32_t sb = smem_u32(smem);
    const int tid = threadIdx.x;
    const int wid = tid >> 5;
    const int lane = tid & 31;
    const int wm = wid >> 1;
    const int wn = wid & 1;
    const int m0 = blockIdx.y * BM;
    const int n0 = blockIdx.x * BN;

    const int8_t* __restrict__ A = g_s1c;
    const int8_t* __restrict__ Bw = g_wl;

    // iter = limb*16 + kc  (48 total)
    auto prefetch = [&](int iter, int stage) {
        const int limb = iter >> 4;
        const int kc = iter & 15;
        uint32_t as = sb + stage * STAGE_BYTES;
        uint32_t bs = as + A_BYTES;
        const int8_t* ag = A + (size_t)m0 * 1024 + kc * 64;
#pragma unroll
        for (int j = 0; j < 4; j++) {   // A: 256 rows x 4 segs
            int id = tid + j * 256;
            int row = id >> 2, seg = id & 3;
            cp_async16(as + row * 80 + seg * 16, ag + (size_t)row * 1024 + seg * 16);
        }
        const int8_t* bg = Bw + ((size_t)limb << 20) + (size_t)n0 * 1024 + kc * 64;
#pragma unroll
        for (int j = 0; j < 2; j++) {   // B: 128 rows x 4 segs
            int id = tid + j * 256;
            int row = id >> 2, seg = id & 3;
            cp_async16(bs + row * 80 + seg * 16, bg + (size_t)row * 1024 + seg * 16);
        }
    };

    int32_t acc[4][8][4];
#pragma unroll
    for (int i = 0; i < 4; i++)
#pragma unroll
        for (int j = 0; j < 8; j++)
#pragma unroll
            for (int q = 0; q < 4; q++) acc[i][j][q] = 0;

    // ldmatrix lane addressing (stride-80 rows, verified conflict-free)
    const uint32_t a_loff = (lane & 15) * 80 + (lane >> 4) * 16;
    const uint32_t b_loff = ((lane & 7) + ((lane >> 4) * 8)) * 80 + (((lane >> 3) & 1) * 16);

    prefetch(0, 0);
    CP_COMMIT();
    prefetch(1, 1);
    CP_COMMIT();

    for (int it = 0; it < 48; it++) {
        if (it < 47) { CP_WAIT(1); } else { CP_WAIT(0); }
        __syncthreads();

        const uint32_t as = sb + (it % 3) * STAGE_BYTES;
        const uint32_t bs = as + A_BYTES;

#pragma unroll
        for (int ks = 0; ks < 2; ks++) {     // two K=32 steps per 64B chunk
            uint32_t af[4][4];
#pragma unroll
            for (int mi = 0; mi < 4; mi++)
                ldm_x4(af[mi], as + (wm * 64 + mi * 16) * 80 + ks * 32 + a_loff);
#pragma unroll
            for (int p = 0; p < 4; p++) {    // 16 n-rows per x4 (two n8 frags)
                uint32_t bf[4];
                ldm_x4(bf, bs + (wn * 64 + p * 16) * 80 + ks * 32 + b_loff);
#pragma unroll
                for (int mi = 0; mi < 4; mi++) {
                    imma16832(acc[mi][2 * p], af[mi], bf[0], bf[1]);
                    imma16832(acc[mi][2 * p + 1], af[mi], bf[2], bf[3]);
                }
            }
        }

        // digit fixup between limb passes: acc <<= 8
        if (it == 15 || it == 31) {
#pragma unroll
            for (int i = 0; i < 4; i++)
#pragma unroll
                for (int j = 0; j < 8; j++)
#pragma unroll
                    for (int q = 0; q < 4; q++) acc[i][j][q] <<= 8;
        }

        if (it + 2 < 48) {
            prefetch(it + 2, (it + 2) % 3);
            CP_COMMIT();
        }
    }

    // ----- fused layer-2 IF scan epilogue -----
    __syncthreads();
    float* sw = reinterpret_cast<float*>(smem) + (size_t)wid * (64 * 65);
    const int qrow = lane >> 2;
    const int qcol = (lane & 3) * 2;
#pragma unroll
    for (int mi = 0; mi < 4; mi++) {
        int t0 = mi * 16 + qrow;
#pragma unroll
        for (int ni = 0; ni < 8; ni++) {
            int cc0 = ni * 8 + qcol;
            sw[t0 * 65 + cc0]           = (float)acc[mi][ni][0] * WINV;
            sw[t0 * 65 + cc0 + 1]       = (float)acc[mi][ni][1] * WINV;
            sw[(t0 + 8) * 65 + cc0]     = (float)acc[mi][ni][2] * WINV;
            sw[(t0 + 8) * 65 + cc0 + 1] = (float)acc[mi][ni][3] * WINV;
        }
    }
    __syncwarp();

    const int b = blockIdx.y * 4 + wm;
#pragma unroll
    for (int grp = 0; grp < 2; grp++) {
        int h = n0 + wn * 64 + grp * 32 + lane;
        float hb = hid_b[h];
        int wordIdx = ((n0 + wn * 64) >> 5) + grp;  // 0..31
        float v = 0.f;
#pragma unroll
        for (int t = 0; t < TT; t++) {
            v += sw[t * 65 + grp * 32 + lane] + hb;
            bool fire = (v >= 1.0f);
            unsigned m = __ballot_sync(0xffffffffu, fire);
            if (lane == 0) g_bits[(size_t)((t << 8) + b) * 32 + wordIdx] = m;
            if (fire) v = 0.f;
        }
    }
}

// ---------------------------------------------------------------------------
// Kernel C: head — output GEMM from bit-packed spikes + layer-3 IF scan +
// spike-rate.  Class-split grid (256 b, 2 halves of 5); k-outer phase 2.
// smem: ows[5*1024] f32 @0, bits[64][32] @20480, inp3[64][5] @28672
// ---------------------------------------------------------------------------
#define NCH 5
#define HEAD_SMEM (20480 + 8192 + 1280)

__global__ __launch_bounds__(256) void head_kernel(
    const float* __restrict__ out_w, const float* __restrict__ out_b,
    float* __restrict__ out) {
    extern __shared__ __align__(128) char hsm[];
    float* ows = reinterpret_cast<float*>(hsm);                  // [5][1024]
    uint32_t* bitsm = reinterpret_cast<uint32_t*>(hsm + 20480);  // [t][word]
    float* inp3 = reinterpret_cast<float*>(hsm + 28672);         // [t][5]

    const int b = blockIdx.x, nh = blockIdx.y, tid = threadIdx.x;
    const int wid = tid >> 5, lane = tid & 31;

    for (int i = tid; i < NCH * H2; i += 256) ows[i] = out_w[nh * NCH * H2 + i];
#pragma unroll
    for (int j = 0; j < 8; j++) {
        int i = tid + j * 256;
        int t = i >> 5, k = i & 31;
        bitsm[i] = g_bits[(size_t)((t << 8) + b) * 32 + k];
    }
    __syncthreads();

    float p[8][NCH];
#pragma unroll
    for (int tt = 0; tt < 8; tt++)
#pragma unroll
        for (int n = 0; n < NCH; n++) p[tt][n] = 0.f;

#pragma unroll 4
    for (int k = 0; k < 32; k++) {
        float w[NCH];
        int i = k * 32 + lane;
#pragma unroll
        for (int n = 0; n < NCH; n++) w[n] = ows[n * H2 + i];
#pragma unroll
        for (int tt = 0; tt < 8; tt++) {
            uint32_t w32 = bitsm[(wid * 8 + tt) * 32 + k];
            float s = (float)((w32 >> lane) & 1u);
#pragma unroll
            for (int n = 0; n < NCH; n++) p[tt][n] += s * w[n];
        }
    }

#pragma unroll
    for (int tt = 0; tt < 8; tt++) {
#pragma unroll
        for (int off = 16; off > 0; off >>= 1) {
#pragma unroll
            for (int n = 0; n < NCH; n++)
                p[tt][n] += __shfl_xor_sync(0xffffffffu, p[tt][n], off);
        }
        if (lane == 0) {
#pragma unroll
            for (int n = 0; n < NCH; n++)
                inp3[(wid * 8 + tt) * NCH + n] = p[tt][n];
        }
    }
    __syncthreads();

    if (tid < NCH) {
        float ob = out_b[nh * NCH + tid];
        float v = 0.f, cnt = 0.f;
#pragma unroll
        for (int t = 0; t < TT; t++) {
            v += inp3[t * NCH + tid] + ob;
            if (v >= 1.0f) { cnt += 1.0f; v = 0.f; }
        }
        out[b * NC + nh * NCH + tid] = cnt * (1.0f / (float)TT);
    }
}

// ---------------------------------------------------------------------------
extern "C" void kernel_launch(void* const* d_in, const int* in_sizes, int n_in,
                              void* d_out, int out_size) {
    const float* x     = (const float*)d_in[0];
    const float* enc_w = (const float*)d_in[1];
    const float* enc_b = (const float*)d_in[2];
    const float* hid_w = (const float*)d_in[3];
    const float* hid_b = (const float*)d_in[4];
    const float* out_w = (const float*)d_in[5];
    const float* out_b = (const float*)d_in[6];
    float* out = (float*)d_out;
    (void)in_sizes; (void)n_in; (void)out_size;

    cudaFuncSetAttribute(gemm2_kernel, cudaFuncAttributeMaxDynamicSharedMemorySize,
                         GEMM_SMEM);
    cudaFuncSetAttribute(head_kernel, cudaFuncAttributeMaxDynamicSharedMemorySize,
                         HEAD_SMEM);

    split_kernel<<<(H1 * H2) / 256, 256>>>(hid_w);
    enc_scan_kernel<<<BB, 256>>>(x, enc_w, enc_b);
    {
        dim3 grid(H2 / BN, (TT * BB) / BM);  // (8, 64)
        gemm2_kernel<<<grid, 256, GEMM_SMEM>>>(hid_b);
    }
    {
        dim3 hgrid(BB, NC / NCH);  // (256, 2)
        head_kernel<<<hgrid, 256, HEAD_SMEM>>>(out_w, out_b, out);
    }
}

// round 17
// speedup vs baseline: 6.4369x; 6.4369x over previous
#include <cuda_runtime.h>
#include <cuda_fp16.h>
#include <cstdint>

#define BB 256
#define CC 128
#define TT 64
#define H1 1024
#define H2 1024
#define NC 10

// Scratch device globals (allocation-free rule)
// s1 layout: [b*64+t][h1]  (m-index b-major so a GEMM tile spans all t)
__device__ __half    g_s1h[(size_t)TT * BB * H1];      // 32MB, fp16 spikes {0,1}
__device__ __half    g_wsplit[(size_t)2 * H2 * H1];    // hid_w 2-way fp16 split (4MB)
__device__ uint32_t  g_bits[(size_t)TT * BB * 32];     // layer-2 spikes, bit-packed (2MB)

// ---------------------------------------------------------------------------
// helpers
// ---------------------------------------------------------------------------
__device__ __forceinline__ uint32_t smem_u32(const void* p) {
    uint32_t a;
    asm("{ .reg .u64 t; cvta.to.shared.u64 t, %1; cvt.u32.u64 %0, t; }"
        : "=r"(a) : "l"(p));
    return a;
}
__device__ __forceinline__ void cp_async16(uint32_t saddr, const void* gaddr) {
    asm volatile("cp.async.ca.shared.global [%0], [%1], 16;\n"
                 :: "r"(saddr), "l"(gaddr));
}
#define CP_COMMIT() asm volatile("cp.async.commit_group;\n" ::: "memory")
#define CP_WAIT(N)  asm volatile("cp.async.wait_group %0;\n" ::"n"(N) : "memory")

__device__ __forceinline__ void ldm_x4(uint32_t* r, uint32_t addr) {
    asm volatile("ldmatrix.sync.aligned.m8n8.x4.shared.b16 {%0,%1,%2,%3}, [%4];"
                 : "=r"(r[0]), "=r"(r[1]), "=r"(r[2]), "=r"(r[3]) : "r"(addr));
}
__device__ __forceinline__ void mma16816(float* c, const uint32_t* a,
                                         uint32_t b0, uint32_t b1) {
    asm volatile(
        "mma.sync.aligned.m16n8k16.row.col.f32.f16.f16.f32 "
        "{%0,%1,%2,%3}, {%4,%5,%6,%7}, {%8,%9}, {%0,%1,%2,%3};"
        : "+f"(c[0]), "+f"(c[1]), "+f"(c[2]), "+f"(c[3])
        : "r"(a[0]), "r"(a[1]), "r"(a[2]), "r"(a[3]), "r"(b0), "r"(b1));
}

// ---------------------------------------------------------------------------
// Kernel 0: split hid_w (fp32) into 2 fp16 limbs: w ~= b0 + b1
// ---------------------------------------------------------------------------
__global__ __launch_bounds__(256) void split_kernel(const float* __restrict__ w) {
    int i = blockIdx.x * 256 + threadIdx.x;
    float v = w[i];
    __half b0 = __float2half_rn(v);
    float r1 = v - __half2float(b0);
    __half b1 = __float2half_rn(r1);
    g_wsplit[i] = b0;
    g_wsplit[(1 << 20) + i] = b1;
}

// ---------------------------------------------------------------------------
// Kernel A: encoder + layer-1 IF scan (enc_w rank-1). One block per b.
// ---------------------------------------------------------------------------
__global__ __launch_bounds__(256) void enc_scan_kernel(
    const float* __restrict__ x, const float* __restrict__ enc_w,
    const float* __restrict__ enc_b) {
    __shared__ float S[TT];
    __shared__ float red[256];
    int b = blockIdx.x, tid = threadIdx.x;
    const float* xb = x + (size_t)b * CC * TT;
    int t = tid & 63, grp = tid >> 6;
    float a = 0.f;
#pragma unroll
    for (int c = 0; c < 32; c++) a += xb[(grp * 32 + c) * TT + t];
    red[tid] = a;
    __syncthreads();
    if (tid < 64) S[tid] = red[tid] + red[tid + 64] + red[tid + 128] + red[tid + 192];
    __syncthreads();

#pragma unroll
    for (int hh = 0; hh < 4; hh++) {
        int h = hh * 256 + tid;
        float vh = enc_w[(size_t)h * CC];
        float eb = enc_b[h];
        float v = 0.f;
#pragma unroll
        for (int tt = 0; tt < TT; tt++) {
            v += vh * S[tt] + eb;
            float s = (v >= 1.0f) ? 1.0f : 0.0f;
            g_s1h[(size_t)(((b << 6) + tt) << 10) + h] = __float2half_rn(s);
            if (v >= 1.0f) v = 0.f;
        }
    }
}

// ---------------------------------------------------------------------------
// Kernel B: fp16 HMMA GEMM + fused layer-2 IF scan epilogue.
// BM=128 (2 b x 64 t) x BN=128, BK=32, 256 thr / 8 warps (warp 32x64),
// acc 64 regs -> __launch_bounds__(256,2): TWO CTAs co-resident per SM so
// each CTA's barriers/waits are hidden by the other's compute.
// 2 fp16 weight limbs, 3-stage cp.async, one syncthreads per chunk.
// Accumulation order identical to the 241.9us kernel.
// Epilogue: whole CTA dumps to smem tile [128][132] (pad 4 mod 32), warp w
// scans (b = wid>>2, h-group = wid&3) columns, ballot-packs into g_bits.
// ---------------------------------------------------------------------------
#define BM 128
#define BN 128
#define BK 32
#define A_BYTES (BM * 80)                    // 10240 (stride-40 fp16 rows)
#define B_BYTES (BN * 80)                    // 10240 per limb
#define STAGE_BYTES (A_BYTES + 2 * B_BYTES)  // 30720
#define GEMM_SMEM (3 * STAGE_BYTES)          // 92160 (>= 128*132*4 epilogue)

__global__ __launch_bounds__(256, 2) void gemm2_kernel(const float* __restrict__ hid_b) {
    extern __shared__ __align__(128) char smem[];
    const uint32_t sb = smem_u32(smem);
    const int tid = threadIdx.x;
    const int wid = tid >> 5;
    const int lane = tid & 31;
    const int wm = wid >> 1;   // 0..3 -> m offset wm*32
    const int wn = wid & 1;    // 0..1 -> n offset wn*64
    const int m0 = blockIdx.y * BM;
    const int n0 = blockIdx.x * BN;

    const __half* __restrict__ A = g_s1h;
    const __half* __restrict__ Bw = g_wsplit;

    auto prefetch = [&](int chunk, int stage) {
        uint32_t as = sb + stage * STAGE_BYTES;
        uint32_t bs = as + A_BYTES;
        const __half* ag = A + (size_t)m0 * 1024 + chunk * BK;
#pragma unroll
        for (int j = 0; j < 2; j++) {   // A: 128 rows x 4 segs = 512 tasks
            int id = tid + j * 256;
            int row = id >> 2, c = id & 3;
            cp_async16(as + row * 80 + c * 16, ag + (size_t)row * 1024 + c * 8);
        }
#pragma unroll
        for (int j = 0; j < 4; j++) {   // B: 2 limbs x 128 rows x 4 = 1024 tasks
            int id = tid + j * 256;
            int limb = id >> 9;
            int rem = id & 511;
            int nrow = rem >> 2, c = rem & 3;
            cp_async16(bs + limb * B_BYTES + nrow * 80 + c * 16,
                       Bw + ((size_t)limb << 20) + (size_t)(n0 + nrow) * 1024 +
                           chunk * BK + c * 8);
        }
    };

    float acc[2][8][4];
#pragma unroll
    for (int i = 0; i < 2; i++)
#pragma unroll
        for (int j = 0; j < 8; j++)
#pragma unroll
            for (int q = 0; q < 4; q++) acc[i][j][q] = 0.f;

    const int j8 = lane >> 3, r8 = lane & 7;
    const uint32_t a_off = ((j8 & 1) * 8 + r8) * 80 + (j8 >> 1) * 16;
    const uint32_t b_off = ((j8 >> 1) * 8 + r8) * 80 + (j8 & 1) * 16;

    prefetch(0, 0);
    CP_COMMIT();
    prefetch(1, 1);
    CP_COMMIT();

    for (int c = 0; c < 32; c++) {
        if (c < 31) { CP_WAIT(1); } else { CP_WAIT(0); }
        __syncthreads();

        const uint32_t as = sb + (c % 3) * STAGE_BYTES;
        const uint32_t bs = as + A_BYTES;

#pragma unroll
        for (int ks = 0; ks < 2; ks++) {
            uint32_t af[2][4];
#pragma unroll
            for (int mi = 0; mi < 2; mi++)
                ldm_x4(af[mi], as + (wm * 32 + mi * 16) * 80 + ks * 32 + a_off);
#pragma unroll
            for (int limb = 0; limb < 2; limb++) {
                uint32_t bf[4][4];
#pragma unroll
                for (int p = 0; p < 4; p++)
                    ldm_x4(bf[p], bs + limb * B_BYTES +
                                      (wn * 64 + p * 16) * 80 + ks * 32 + b_off);
#pragma unroll
                for (int mi = 0; mi < 2; mi++)
#pragma unroll
                    for (int p = 0; p < 4; p++) {
                        mma16816(acc[mi][2 * p], af[mi], bf[p][0], bf[p][1]);
                        mma16816(acc[mi][2 * p + 1], af[mi], bf[p][2], bf[p][3]);
                    }
            }
        }

        if (c + 2 < 32) {
            prefetch(c + 2, (c + 2) % 3);
            CP_COMMIT();
        }
    }

    // ----- fused layer-2 IF scan epilogue (whole-CTA tile) -----
    __syncthreads();  // all warps done reading pipeline buffers
    float* sw = reinterpret_cast<float*>(smem);
    const int S = 132;  // 132 mod 32 = 4 -> conflict-free quad writes
    const int qrow = lane >> 2;
    const int qcol = (lane & 3) * 2;
#pragma unroll
    for (int mi = 0; mi < 2; mi++) {
        int r0 = wm * 32 + mi * 16 + qrow;
#pragma unroll
        for (int ni = 0; ni < 8; ni++) {
            int c0 = wn * 64 + ni * 8 + qcol;
            sw[r0 * S + c0]           = acc[mi][ni][0];
            sw[r0 * S + c0 + 1]       = acc[mi][ni][1];
            sw[(r0 + 8) * S + c0]     = acc[mi][ni][2];
            sw[(r0 + 8) * S + c0 + 1] = acc[mi][ni][3];
        }
    }
    __syncthreads();

    const int bloc = wid >> 2;              // 0..1
    const int b = blockIdx.y * 2 + bloc;
    const int hgrp = wid & 3;               // 0..3
    const float hb = hid_b[n0 + hgrp * 32 + lane];
    const int wordIdx = blockIdx.x * 4 + hgrp;  // 0..31
    float v = 0.f;
#pragma unroll
    for (int t = 0; t < TT; t++) {
        v += sw[(bloc * 64 + t) * S + hgrp * 32 + lane] + hb;
        bool fire = (v >= 1.0f);
        unsigned m = __ballot_sync(0xffffffffu, fire);
        if (lane == 0) g_bits[(size_t)((t << 8) + b) * 32 + wordIdx] = m;
        if (fire) v = 0.f;
    }
}

// ---------------------------------------------------------------------------
// Kernel C: head — output GEMM from bit-packed spikes + layer-3 IF scan +
// spike-rate.  Class-split grid (256 b, 2 halves of 5); k-outer phase 2.
// smem: ows[5*1024] f32 @0, bits[64][32] @20480, inp3[64][5] @28672
// ---------------------------------------------------------------------------
#define NCH 5
#define HEAD_SMEM (20480 + 8192 + 1280)

__global__ __launch_bounds__(256) void head_kernel(
    const float* __restrict__ out_w, const float* __restrict__ out_b,
    float* __restrict__ out) {
    extern __shared__ __align__(128) char hsm[];
    float* ows = reinterpret_cast<float*>(hsm);                  // [5][1024]
    uint32_t* bitsm = reinterpret_cast<uint32_t*>(hsm + 20480);  // [t][word]
    float* inp3 = reinterpret_cast<float*>(hsm + 28672);         // [t][5]

    const int b = blockIdx.x, nh = blockIdx.y, tid = threadIdx.x;
    const int wid = tid >> 5, lane = tid & 31;

    for (int i = tid; i < NCH * H2; i += 256) ows[i] = out_w[nh * NCH * H2 + i];
#pragma unroll
    for (int j = 0; j < 8; j++) {
        int i = tid + j * 256;
        int t = i >> 5, k = i & 31;
        bitsm[i] = g_bits[(size_t)((t << 8) + b) * 32 + k];
    }
    __syncthreads();

    float p[8][NCH];
#pragma unroll
    for (int tt = 0; tt < 8; tt++)
#pragma unroll
        for (int n = 0; n < NCH; n++) p[tt][n] = 0.f;

#pragma unroll 4
    for (int k = 0; k < 32; k++) {
        float w[NCH];
        int i = k * 32 + lane;
#pragma unroll
        for (int n = 0; n < NCH; n++) w[n] = ows[n * H2 + i];
#pragma unroll
        for (int tt = 0; tt < 8; tt++) {
            uint32_t w32 = bitsm[(wid * 8 + tt) * 32 + k];
            float s = (float)((w32 >> lane) & 1u);
#pragma unroll
            for (int n = 0; n < NCH; n++) p[tt][n] += s * w[n];
        }
    }

#pragma unroll
    for (int tt = 0; tt < 8; tt++) {
#pragma unroll
        for (int off = 16; off > 0; off >>= 1) {
#pragma unroll
            for (int n = 0; n < NCH; n++)
                p[tt][n] += __shfl_xor_sync(0xffffffffu, p[tt][n], off);
        }
        if (lane == 0) {
#pragma unroll
            for (int n = 0; n < NCH; n++)
                inp3[(wid * 8 + tt) * NCH + n] = p[tt][n];
        }
    }
    __syncthreads();

    if (tid < NCH) {
        float ob = out_b[nh * NCH + tid];
        float v = 0.f, cnt = 0.f;
#pragma unroll
        for (int t = 0; t < TT; t++) {
            v += inp3[t * NCH + tid] + ob;
            if (v >= 1.0f) { cnt += 1.0f; v = 0.f; }
        }
        out[b * NC + nh * NCH + tid] = cnt * (1.0f / (float)TT);
    }
}

// ---------------------------------------------------------------------------
extern "C" void kernel_launch(void* const* d_in, const int* in_sizes, int n_in,
                              void* d_out, int out_size) {
    const float* x     = (const float*)d_in[0];
    const float* enc_w = (const float*)d_in[1];
    const float* enc_b = (const float*)d_in[2];
    const float* hid_w = (const float*)d_in[3];
    const float* hid_b = (const float*)d_in[4];
    const float* out_w = (const float*)d_in[5];
    const float* out_b = (const float*)d_in[6];
    float* out = (float*)d_out;
    (void)in_sizes; (void)n_in; (void)out_size;

    cudaFuncSetAttribute(gemm2_kernel, cudaFuncAttributeMaxDynamicSharedMemorySize,
                         GEMM_SMEM);
    cudaFuncSetAttribute(head_kernel, cudaFuncAttributeMaxDynamicSharedMemorySize,
                         HEAD_SMEM);

    split_kernel<<<(H1 * H2) / 256, 256>>>(hid_w);
    enc_scan_kernel<<<BB, 256>>>(x, enc_w, enc_b);
    {
        dim3 grid(H2 / BN, (TT * BB) / BM);  // (8, 128)
        gemm2_kernel<<<grid, 256, GEMM_SMEM>>>(hid_b);
    }
    {
        dim3 hgrid(BB, NC / NCH);  // (256, 2)
        head_kernel<<<hgrid, 256, HEAD_SMEM>>>(out_w, out_b, out);
    }
}